// round 14
// baseline (speedup 1.0000x reference)
#include <cuda_runtime.h>

#define BATCH   32
#define TSTEPS  1024
#define COLS    2048
#define SPLIT   16             /* column-blocks per batch row          */
#define THREADS 32             /* ONE warp per CTA: no bar, no smem    */
#define V       4              /* columns per thread (float4)          */
#define ROW4    (COLS / 4)     /* row stride in float4 = 512           */
#define DPF     8              /* x prefetch depth (time steps)        */
#define KREL    8              /* relay prefetch queue depth           */

/* One 64-bit word per (batch,block,t): hi32 = ready flag, lo32 = float bits.
   Flag and value share a word -> relaxed 64-bit atomics are sufficient.  */
__device__ unsigned long long g_relay[BATCH * SPLIT * TSTEPS];   /* 4 MB */

__device__ __forceinline__ unsigned long long ld_rlx(const unsigned long long* p) {
    unsigned long long v;
    asm volatile("ld.relaxed.gpu.global.b64 %0, [%1];" : "=l"(v) : "l"(p) : "memory");
    return v;
}
__device__ __forceinline__ void st_rlx(unsigned long long* p, unsigned long long v) {
    asm volatile("st.relaxed.gpu.global.b64 [%0], %1;" :: "l"(p), "l"(v) : "memory");
}

__device__ __forceinline__ float smix(float a, float b) {
    float d = a - b;                       /* a - b          */
    float e = __expf(-d);                  /* MUFU.EX2 path  */
    float p = __fdividef(1.0f, 1.0f + e);  /* MUFU.RCP path  */
    return fmaf(p, d, b);                  /* b + p*(a-b)    */
}

#define TAGV(f) ((1ull << 32) | (unsigned long long)__float_as_uint(f))

__global__ __launch_bounds__(THREADS)
void softscan_kernel(const float* __restrict__ x, float* __restrict__ out) {
    const int s    = blockIdx.x;           /* column-block within batch */
    const int b    = blockIdx.y;
    const int tid  = threadIdx.x;          /* == lane                   */
    const int col0 = (s * THREADS + tid) * V;

    const float4* xp = (const float4*)(x   + (size_t)b * TSTEPS * COLS + col0);
    float4*       op = (float4*)      (out + (size_t)b * TSTEPS * COLS + col0);

    const int lane_id = b * SPLIT + s;
    unsigned long long*       my_slot = g_relay + (size_t)lane_id * TSTEPS;
    const unsigned long long* src     = g_relay + (size_t)(lane_id - 1) * TSTEPS;

    const bool producer = (tid == THREADS - 1) && (s != SPLIT - 1);
    const bool consumer = (tid == 0) && (s != 0);
    const bool firstcol = (tid == 0) && (s == 0);

    /* ---- t = 0: carry = x[b,0,:] ---- */
    float4 c = __ldcs(xp);
    __stcs(op, c);
    if (producer) st_rlx(my_slot, TAGV(c.w));

    /* x prefetch ring: buf[k] holds row t where (t-1)&7 == k */
    float4 buf[DPF];
    #pragma unroll
    for (int k = 0; k < DPF; ++k)
        buf[k] = __ldcs(xp + (size_t)(k + 1) * ROW4);

    /* relay prefetch queue: pend[k] holds src slot t-1 where (t-1)&7 == k */
    unsigned long long pend[KREL];
    if (consumer) {
        #pragma unroll
        for (int k = 0; k < KREL; ++k) pend[k] = ld_rlx(src + k);
    }

    for (int tb = 1; tb < TSTEPS; tb += DPF) {
        #pragma unroll
        for (int k = 0; k < DPF; ++k) {
            const int t = tb + k;          /* (t-1)&7 == k by construction */
            if (t >= TSTEPS) break;

            float4 xv = buf[k];
            if (t + DPF < TSTEPS)
                buf[k] = __ldcs(xp + (size_t)(t + DPF) * ROW4);

            /* left neighbor's carry (col0-1) from step t-1 */
            float left = __shfl_up_sync(0xffffffffu, c.w, 1);
            if (consumer) {
                unsigned long long v = pend[k];
                if (!(v >> 32)) {                       /* warm-up / skew miss */
                    do { v = ld_rlx(src + (t - 1)); } while (!(v >> 32));
                }
                left = __uint_as_float((unsigned)v);
                if (t - 1 + KREL < TSTEPS)              /* refill 8 steps ahead */
                    pend[k] = ld_rlx(src + (t - 1 + KREL));
            }

            /* all 4 mixes read OLD carries -> parallel inside the step */
            float4 nc;
            nc.x = firstcol ? (xv.x + c.x) : (xv.x + smix(c.x, left));
            nc.y = xv.y + smix(c.y, c.x);
            nc.z = xv.z + smix(c.z, c.y);
            nc.w = xv.w + smix(c.w, c.z);
            c = nc;

            __stcs(op + (size_t)t * ROW4, c);
            if (producer) st_rlx(my_slot + t, TAGV(c.w));
        }
    }
}

extern "C" void kernel_launch(void* const* d_in, const int* in_sizes, int n_in,
                              void* d_out, int out_size) {
    const float* x = (const float*)d_in[0];
    float* out = (float*)d_out;

    /* Reset relay flags every launch (captured memset node -> replay-safe). */
    void* relay_ptr = nullptr;
    cudaGetSymbolAddress(&relay_ptr, g_relay);
    cudaMemsetAsync(relay_ptr, 0, sizeof(unsigned long long) * BATCH * SPLIT * TSTEPS, 0);

    /* 512 single-warp CTAs: all co-resident (<=32 CTAs/SM), relay deadlock-free */
    dim3 grid(SPLIT, BATCH);
    softscan_kernel<<<grid, THREADS>>>(x, out);
}

// round 15
// speedup vs baseline: 2.0644x; 2.0644x over previous
#include <cuda_runtime.h>

#define BATCH   32
#define TSTEPS  1024
#define COLS    2048
#define SPLIT   4
#define THREADS 128            /* 4 warps per CTA */
#define V       4              /* columns per thread (float4) */
#define WARPS   (THREADS / 32)
#define ROW4    (COLS / 4)     /* row stride in float4 = 512 */
#define DPF     8              /* x prefetch depth (steps) */
#define KREL    8              /* relay prefetch queue depth */
#define LAG     12             /* enforced consumer lag (> KREL+visibility) */
#define TMAIN   1017           /* main loop covers t = 1..1016 (127 chunks of 8) */

/* One 64-bit word per (batch,block,t): hi32 = ready flag, lo32 = float bits. */
__device__ unsigned long long g_relay[BATCH * SPLIT * TSTEPS];

__device__ __forceinline__ unsigned long long ld_rlx(const unsigned long long* p) {
    unsigned long long v;
    asm volatile("ld.relaxed.gpu.global.b64 %0, [%1];" : "=l"(v) : "l"(p) : "memory");
    return v;
}
__device__ __forceinline__ void st_rlx(unsigned long long* p, unsigned long long v) {
    asm volatile("st.relaxed.gpu.global.b64 [%0], %1;" :: "l"(p), "l"(v) : "memory");
}

__device__ __forceinline__ float smix(float a, float b) {
    float d = a - b;
    float e = __expf(-d);                  /* MUFU.EX2 */
    float p = __fdividef(1.0f, 1.0f + e);  /* MUFU.RCP */
    return fmaf(p, d, b);
}

#define TAGV(f) ((1ull << 32) | (unsigned long long)__float_as_uint(f))

__global__ __launch_bounds__(THREADS, 1)
void softscan_kernel(const float* __restrict__ x, float* __restrict__ out) {
    const int s    = blockIdx.x;
    const int b    = blockIdx.y;
    const int tid  = threadIdx.x;
    const int lane = tid & 31;
    const int warp = tid >> 5;
    const int col0 = (s * THREADS + tid) * V;

    __shared__ float sh[2][WARPS];         /* double-buffered warp seams */

    const float4* xp = (const float4*)(x   + (size_t)b * TSTEPS * COLS + col0);
    float4*       op = (float4*)      (out + (size_t)b * TSTEPS * COLS + col0);

    const int lane_id = b * SPLIT + s;
    unsigned long long*       my_slot = g_relay + (size_t)lane_id * TSTEPS;
    const unsigned long long* src     = g_relay + (size_t)(lane_id - 1) * TSTEPS;

    const bool producer = (tid == THREADS - 1) && (s != SPLIT - 1);
    const bool consumer = (tid == 0) && (s != 0);
    const bool firstcol = (tid == 0) && (s == 0);

    /* ---- t = 0 ---- */
    float4 c = __ldcs(xp);
    __stcs(op, c);
    if (lane == 31) sh[0][warp] = c.w;
    if (producer) st_rlx(my_slot, TAGV(c.w));

    /* x prefetch ring: buf[k] holds row t where (t-1)&7 == k */
    float4 buf[DPF];
    #pragma unroll
    for (int k = 0; k < DPF; ++k)
        buf[k] = __ldcs(xp + (size_t)(k + 1) * ROW4);

    /* Warm-up lag enforcement: wait ONCE until upstream is LAG steps ahead.
       Afterwards every pend prefetch hits an already-written slot. */
    unsigned long long pend[KREL];
    if (consumer) {
        while (!(ld_rlx(src + LAG) >> 32)) { }
        #pragma unroll
        for (int k = 0; k < KREL; ++k) pend[k] = ld_rlx(src + k);
    }
    __syncthreads();

    /* ---- main: t = 1..1016, 127 full chunks of 8, branch-free body ---- */
    for (int tb = 1; tb < TMAIN; tb += DPF) {
        #pragma unroll
        for (int k = 0; k < DPF; ++k) {
            const int t = tb + k;          /* (t-1)&7 == k */

            float4 xv = buf[k];
            int pf = t + DPF; if (pf > TSTEPS - 1) pf = TSTEPS - 1;   /* SEL */
            buf[k] = __ldcs(xp + (size_t)pf * ROW4);

            float left = __shfl_up_sync(0xffffffffu, c.w, 1);
            if (lane == 0) {
                if (warp > 0) {
                    left = sh[(t - 1) & 1][warp - 1];
                } else if (consumer) {
                    unsigned long long v = pend[k];
                    if (!(v >> 32)) {      /* should never fire after warm-up */
                        do { v = ld_rlx(src + (t - 1)); } while (!(v >> 32));
                    }
                    left = __uint_as_float((unsigned)v);
                    int ri = t - 1 + KREL; if (ri > TSTEPS - 1) ri = TSTEPS - 1;
                    pend[k] = ld_rlx(src + ri);
                }
            }

            float4 nc;
            nc.x = firstcol ? (xv.x + c.x) : (xv.x + smix(c.x, left));
            nc.y = xv.y + smix(c.y, c.x);
            nc.z = xv.z + smix(c.z, c.y);
            nc.w = xv.w + smix(c.w, c.z);
            c = nc;

            __stcs(op + (size_t)t * ROW4, c);
            if (lane == 31) sh[t & 1][warp] = c.w;
            if (producer) st_rlx(my_slot + t, TAGV(c.w));
            __syncthreads();
        }
    }

    /* ---- epilogue: t = 1017..1023 (7 steps), no x prefetch ---- */
    #pragma unroll
    for (int k = 0; k < 7; ++k) {
        const int t = TMAIN + k;           /* (t-1)&7 == k */

        float4 xv = buf[k];

        float left = __shfl_up_sync(0xffffffffu, c.w, 1);
        if (lane == 0) {
            if (warp > 0) {
                left = sh[(t - 1) & 1][warp - 1];
            } else if (consumer) {
                unsigned long long v = pend[k];
                if (!(v >> 32)) {
                    do { v = ld_rlx(src + (t - 1)); } while (!(v >> 32));
                }
                left = __uint_as_float((unsigned)v);
            }
        }

        float4 nc;
        nc.x = firstcol ? (xv.x + c.x) : (xv.x + smix(c.x, left));
        nc.y = xv.y + smix(c.y, c.x);
        nc.z = xv.z + smix(c.z, c.y);
        nc.w = xv.w + smix(c.w, c.z);
        c = nc;

        __stcs(op + (size_t)t * ROW4, c);
        if (lane == 31) sh[t & 1][warp] = c.w;
        if (producer) st_rlx(my_slot + t, TAGV(c.w));
        __syncthreads();
    }
}

extern "C" void kernel_launch(void* const* d_in, const int* in_sizes, int n_in,
                              void* d_out, int out_size) {
    const float* x = (const float*)d_in[0];
    float* out = (float*)d_out;

    /* Reset relay flags each launch (captured memset node -> replay-safe). */
    void* relay_ptr = nullptr;
    cudaGetSymbolAddress(&relay_ptr, g_relay);
    cudaMemsetAsync(relay_ptr, 0, sizeof(unsigned long long) * BATCH * SPLIT * TSTEPS, 0);

    dim3 grid(SPLIT, BATCH);   /* 128 CTAs <= 148 SMs: single wave, deadlock-free */
    softscan_kernel<<<grid, THREADS>>>(x, out);
}